// round 3
// baseline (speedup 1.0000x reference)
#include <cuda_runtime.h>
#include <math.h>

#define BATCH 4
#define HWIN (1024*1024)

// ---------------- scratch (static device memory, no allocs) ----------------
__device__ float g_x0[BATCH*3*256*256];       // resized input
__device__ float g_x1[BATCH*16*128*128];
__device__ float g_x2[BATCH*32*64*64];
__device__ float g_x3[BATCH*64*32*32];
__device__ float g_x4[BATCH*128*16*16];
__device__ float g_codes[BATCH*512];
__device__ float g_wts[BATCH*3];
__device__ float g_vert[BATCH*99];
// LUT in gather-friendly layout: [b][i(33)][j(33)][k0(32)][dk(2)*4ch] -> 32B blocks
__device__ __align__(32) float g_lut[BATCH*33*33*32*8];

// ---------------- 1) bilinear 1024 -> 256 (fracs are exactly 0.5) ----------
__global__ void resize_kernel(const float* __restrict__ in, float* __restrict__ out){
    int t = blockIdx.x*blockDim.x + threadIdx.x;       // < BATCH*3*256*256
    int ox = t & 255, oy = (t>>8) & 255;
    int pc = t >> 16;                                  // b*3+c plane index
    const float* ip = in + (size_t)pc * HWIN;
    int y0 = 4*oy+1, x0 = 4*ox+1;
    const float* r0 = ip + (size_t)y0*1024 + x0;
    out[t] = 0.25f*(r0[0] + r0[1] + r0[1024] + r0[1025]);
}

// ---- 2) conv3x3 s2 p1 + bias + LeakyReLU(0.2) + InstanceNorm (affine) -----
// one CTA per (b, cout) plane; 512 threads
__global__ void conv_block(const float* __restrict__ in, float* __restrict__ out,
                           const float* __restrict__ w, const float* __restrict__ bias,
                           const float* __restrict__ gamma, const float* __restrict__ beta,
                           int Cin, int Cout, int Hin, int Hout){
    __shared__ float ws[576];        // up to Cin=64 * 9
    __shared__ float rs[512];
    __shared__ float rs2[512];
    int tid = threadIdx.x;
    int co = blockIdx.x % Cout;
    int b  = blockIdx.x / Cout;
    int nw = Cin*9;
    for (int i = tid; i < nw; i += blockDim.x) ws[i] = w[co*nw + i];
    __syncthreads();

    const float* inb = in + (size_t)b*Cin*Hin*Hin;
    int npx = Hout*Hout;
    int nsl = (npx + 511) >> 9;
    float v[32];
    float s = 0.f, s2 = 0.f;
    for (int sl = 0; sl < nsl; ++sl){
        int p = tid + (sl << 9);
        if (p < npx){
            int oy = p / Hout, ox = p - oy*Hout;
            int iy = 2*oy - 1, ix = 2*ox - 1;
            float acc = bias[co];
            const float* wp = ws;
            const float* ip = inb;
            for (int ci = 0; ci < Cin; ++ci, wp += 9, ip += Hin*Hin){
                #pragma unroll
                for (int ky = 0; ky < 3; ++ky){
                    int y = iy + ky;
                    if ((unsigned)y >= (unsigned)Hin) continue;
                    const float* row = ip + y*Hin;
                    #pragma unroll
                    for (int kx = 0; kx < 3; ++kx){
                        int x = ix + kx;
                        if ((unsigned)x >= (unsigned)Hin) continue;
                        acc += row[x]*wp[ky*3+kx];
                    }
                }
            }
            acc = acc >= 0.f ? acc : 0.2f*acc;   // LeakyReLU
            v[sl] = acc; s += acc; s2 += acc*acc;
        }
    }
    rs[tid] = s; rs2[tid] = s2; __syncthreads();
    for (int st = 256; st > 0; st >>= 1){
        if (tid < st){ rs[tid] += rs[tid+st]; rs2[tid] += rs2[tid+st]; }
        __syncthreads();
    }
    float inv  = 1.f/(float)npx;
    float mean = rs[0]*inv;
    float var  = rs2[0]*inv - mean*mean;        // biased variance (jnp.var)
    float rstd = rsqrtf(var + 1e-5f);
    float A  = gamma[co]*rstd;
    float Bc = beta[co] - mean*A;
    float* ob = out + (size_t)blockIdx.x*npx;   // (b*Cout+co)*npx
    for (int sl = 0; sl < nsl; ++sl){
        int p = tid + (sl << 9);
        if (p < npx) ob[p] = v[sl]*A + Bc;
    }
}

// ---- 3) block5: conv(no norm) + LeakyReLU + AdaptiveAvgPool(2) fused ------
// one CTA per (b, co) plane of 8x8; 64 threads
__global__ void conv5_pool(const float* __restrict__ in, const float* __restrict__ w,
                           const float* __restrict__ bias, float* __restrict__ codes){
    __shared__ float ws[1152];      // 128*9
    __shared__ float pv[64];
    int tid = threadIdx.x;
    int b  = blockIdx.x >> 7;
    int co = blockIdx.x & 127;
    for (int i = tid; i < 1152; i += 64) ws[i] = w[co*1152 + i];
    __syncthreads();
    const float* inb = in + (size_t)b*128*256;   // 128 ch * 16*16
    int oy = tid >> 3, ox = tid & 7;
    int iy = 2*oy - 1, ix = 2*ox - 1;
    float acc = bias[co];
    const float* wp = ws;
    const float* ip = inb;
    for (int ci = 0; ci < 128; ++ci, wp += 9, ip += 256){
        #pragma unroll
        for (int ky = 0; ky < 3; ++ky){
            int y = iy + ky; if ((unsigned)y >= 16u) continue;
            const float* row = ip + y*16;
            #pragma unroll
            for (int kx = 0; kx < 3; ++kx){
                int x = ix + kx; if ((unsigned)x >= 16u) continue;
                acc += row[x]*wp[ky*3+kx];
            }
        }
    }
    acc = acc >= 0.f ? acc : 0.2f*acc;
    pv[tid] = acc; __syncthreads();
    if (tid < 4){
        int h1 = tid >> 1, w1 = tid & 1;
        float sum = 0.f;
        #pragma unroll
        for (int yy = 0; yy < 4; ++yy)
            #pragma unroll
            for (int xx = 0; xx < 4; ++xx)
                sum += pv[(h1*4+yy)*8 + w1*4+xx];
        codes[b*512 + co*4 + h1*2 + w1] = sum*(1.f/16.f);
    }
}

// ---- 4) FC heads: weights = codes@lw.T+lb ; vertices via softmax+cumsum ---
__global__ void fc_kernel(const float* __restrict__ codes,
                          const float* __restrict__ lw, const float* __restrict__ lb,
                          const float* __restrict__ aw, const float* __restrict__ ab,
                          float* __restrict__ gw, float* __restrict__ gvert,
                          float* __restrict__ ow, float* __restrict__ ov){
    __shared__ float cs[512];
    __shared__ float iv[96];
    int b = blockIdx.x, tid = threadIdx.x;   // 128 threads
    for (int i = tid; i < 512; i += 128) cs[i] = codes[b*512 + i];
    __syncthreads();
    if (tid < 96){
        float acc = ab[tid];
        const float* ar = aw + tid*512;
        for (int k = 0; k < 512; ++k) acc += cs[k]*ar[k];
        iv[tid] = acc;
    } else if (tid < 99){
        int o = tid - 96;
        float acc = lb[o];
        const float* lr = lw + o*512;
        for (int k = 0; k < 512; ++k) acc += cs[k]*lr[k];
        gw[b*3+o] = acc; ow[b*3+o] = acc;
    }
    __syncthreads();
    if (tid < 3){
        const float* x = iv + tid*32;
        float m = x[0];
        for (int i = 1; i < 32; ++i) m = fmaxf(m, x[i]);
        float ssum = 0.f;
        for (int i = 0; i < 32; ++i) ssum += expf(x[i]-m);
        float inv = 1.f/ssum;
        int base = (b*3 + tid)*33;
        gvert[base] = 0.f; ov[base] = 0.f;
        float cum = 0.f;
        for (int i = 0; i < 32; ++i){
            cum += expf(x[i]-m)*inv;
            gvert[base+1+i] = cum; ov[base+1+i] = cum;
        }
    }
}

// ---- 5) combined LUT in pair-duplicated layout ----------------------------
// slot = dk*4 + c ; element (b,i,j,k0,slot)
__global__ void lutgen(const float* __restrict__ gw, const float* __restrict__ bw,
                       float* __restrict__ lut){
    int t = blockIdx.x*blockDim.x + threadIdx.x;   // < BATCH*33*33*32*8
    int slot = t & 7;
    int cc = slot & 3, dk = slot >> 2;
    int k  = (t >> 3) & 31;
    int r  = t >> 8;                               // (b*33+i)*33+j
    int j  = r % 33; r /= 33;
    int i  = r % 33; int b = r / 33;
    float val = 0.f;
    if (cc < 3){
        int row = ((cc*33 + i)*33 + j)*33 + (k + dk);
        const float* br = bw + row*3;
        const float* wv = gw + b*3;
        val = wv[0]*br[0] + wv[1]*br[1] + wv[2]*br[2];
    }
    lut[t] = val;
}

// ---- 6) AiLUT transform: searchsorted + trilerp + clamp -------------------
__device__ __forceinline__ float coord_of(float p, const float* v){
    int lo = 0, hi = 33;              // first idx with v[idx] > p (side='right')
    #pragma unroll
    for (int it = 0; it < 6; ++it){
        if (lo < hi){
            int mid = (lo + hi) >> 1;
            if (v[mid] <= p) lo = mid + 1; else hi = mid;
        }
    }
    int idx = lo < 1 ? 1 : (lo > 32 ? 32 : lo);
    float vl = v[idx-1], vh = v[idx];
    float f = (p - vl)/(vh - vl + 1e-8f);
    float c = (float)(idx-1) + f;
    return fminf(fmaxf(c, 0.f), 32.f);
}

__global__ void transform_kernel(const float* __restrict__ lq, const float* __restrict__ vert,
                                 const float* __restrict__ lut, float* __restrict__ out){
    __shared__ float sv[99];
    int b   = blockIdx.y;
    int tid = threadIdx.x;
    if (tid < 99) sv[tid] = vert[b*99 + tid];
    __syncthreads();
    const float* ib = lq  + (size_t)b*3*HWIN;
    float*       ob = out + (size_t)b*3*HWIN;
    const float* lb = lut + (size_t)b*278784;    // 33*33*32*8
    int base = blockIdx.x*1024 + tid;
    #pragma unroll
    for (int pp = 0; pp < 4; ++pp){
        int n = base + pp*256;
        float r  = ib[n];
        float g  = ib[HWIN + n];
        float bl = ib[2*HWIN + n];
        float cr = coord_of(r,  sv);
        float cg = coord_of(g,  sv + 33);
        float cb = coord_of(bl, sv + 66);
        int i0 = (int)cr; i0 = i0 > 31 ? 31 : i0; float fr = cr - (float)i0;
        int j0 = (int)cg; j0 = j0 > 31 ? 31 : j0; float fg = cg - (float)j0;
        int k0 = (int)cb; k0 = k0 > 31 ? 31 : k0; float fk = cb - (float)k0;
        const float* p00 = lb + ((i0*33 + j0) << 8) + (k0 << 3);
        float w00 = (1.f-fr)*(1.f-fg), w01 = (1.f-fr)*fg;
        float w10 = fr*(1.f-fg),       w11 = fr*fg;
        float a0 = 0.f, a1 = 0.f, a2 = 0.f;
        {   // (i0, j0)
            float4 lo = *(const float4*)p00, hi = *(const float4*)(p00+4);
            a0 += w00*(lo.x + fk*(hi.x-lo.x));
            a1 += w00*(lo.y + fk*(hi.y-lo.y));
            a2 += w00*(lo.z + fk*(hi.z-lo.z));
        }
        {   // (i0, j0+1)
            const float* p = p00 + 256;
            float4 lo = *(const float4*)p, hi = *(const float4*)(p+4);
            a0 += w01*(lo.x + fk*(hi.x-lo.x));
            a1 += w01*(lo.y + fk*(hi.y-lo.y));
            a2 += w01*(lo.z + fk*(hi.z-lo.z));
        }
        {   // (i0+1, j0)
            const float* p = p00 + 33*256;
            float4 lo = *(const float4*)p, hi = *(const float4*)(p+4);
            a0 += w10*(lo.x + fk*(hi.x-lo.x));
            a1 += w10*(lo.y + fk*(hi.y-lo.y));
            a2 += w10*(lo.z + fk*(hi.z-lo.z));
        }
        {   // (i0+1, j0+1)
            const float* p = p00 + 33*256 + 256;
            float4 lo = *(const float4*)p, hi = *(const float4*)(p+4);
            a0 += w11*(lo.x + fk*(hi.x-lo.x));
            a1 += w11*(lo.y + fk*(hi.y-lo.y));
            a2 += w11*(lo.z + fk*(hi.z-lo.z));
        }
        ob[n]          = fminf(fmaxf(a0, 0.f), 1.f);
        ob[HWIN + n]   = fminf(fmaxf(a1, 0.f), 1.f);
        ob[2*HWIN + n] = fminf(fmaxf(a2, 0.f), 1.f);
    }
}

// ---------------------------------------------------------------------------
extern "C" void kernel_launch(void* const* d_in, const int* in_sizes, int n_in,
                              void* d_out, int out_size){
    const float* lq  = (const float*)d_in[0];
    const float* w1  = (const float*)d_in[1];
    const float* b1  = (const float*)d_in[2];
    const float* g1  = (const float*)d_in[3];
    const float* be1 = (const float*)d_in[4];
    const float* w2  = (const float*)d_in[5];
    const float* b2  = (const float*)d_in[6];
    const float* g2  = (const float*)d_in[7];
    const float* be2 = (const float*)d_in[8];
    const float* w3  = (const float*)d_in[9];
    const float* b3  = (const float*)d_in[10];
    const float* g3  = (const float*)d_in[11];
    const float* be3 = (const float*)d_in[12];
    const float* w4  = (const float*)d_in[13];
    const float* b4  = (const float*)d_in[14];
    const float* g4  = (const float*)d_in[15];
    const float* be4 = (const float*)d_in[16];
    const float* w5  = (const float*)d_in[17];
    const float* b5  = (const float*)d_in[18];
    const float* lw  = (const float*)d_in[19];
    const float* lb  = (const float*)d_in[20];
    const float* bw  = (const float*)d_in[21];
    const float* aw  = (const float*)d_in[22];
    const float* ab  = (const float*)d_in[23];
    float* out = (float*)d_out;

    float *x0,*x1,*x2,*x3,*x4,*codes,*wS,*vS,*lutp;
    cudaGetSymbolAddress((void**)&x0,    g_x0);
    cudaGetSymbolAddress((void**)&x1,    g_x1);
    cudaGetSymbolAddress((void**)&x2,    g_x2);
    cudaGetSymbolAddress((void**)&x3,    g_x3);
    cudaGetSymbolAddress((void**)&x4,    g_x4);
    cudaGetSymbolAddress((void**)&codes, g_codes);
    cudaGetSymbolAddress((void**)&wS,    g_wts);
    cudaGetSymbolAddress((void**)&vS,    g_vert);
    cudaGetSymbolAddress((void**)&lutp,  g_lut);

    const size_t OFF_W = (size_t)BATCH*3*HWIN;   // 12,582,912
    const size_t OFF_V = OFF_W + BATCH*3;        // +12

    resize_kernel<<<(BATCH*3*256*256)/256, 256>>>(lq, x0);
    conv_block<<<BATCH*16,  512>>>(x0, x1, w1, b1, g1, be1,  3,  16, 256, 128);
    conv_block<<<BATCH*32,  512>>>(x1, x2, w2, b2, g2, be2, 16,  32, 128,  64);
    conv_block<<<BATCH*64,  512>>>(x2, x3, w3, b3, g3, be3, 32,  64,  64,  32);
    conv_block<<<BATCH*128, 512>>>(x3, x4, w4, b4, g4, be4, 64, 128,  32,  16);
    conv5_pool<<<BATCH*128, 64>>>(x4, w5, b5, codes);
    fc_kernel<<<BATCH, 128>>>(codes, lw, lb, aw, ab, wS, vS, out + OFF_W, out + OFF_V);
    lutgen<<<(BATCH*33*33*32*8)/256, 256>>>(wS, bw, lutp);
    transform_kernel<<<dim3(1024, BATCH), 256>>>(lq, vS, lutp, out);
}

// round 5
// speedup vs baseline: 1.2561x; 1.2561x over previous
#include <cuda_runtime.h>
#include <math.h>

#define BATCH 4
#define HWIN (1024*1024)

// ---------------- scratch (static device memory, no allocs) ----------------
__device__ float g_x0[BATCH*3*256*256];       // resized input
__device__ float g_x1[BATCH*16*128*128];
__device__ float g_x2[BATCH*32*64*64];
__device__ float g_x3[BATCH*64*32*32];
__device__ float g_x4[BATCH*128*16*16];
__device__ float g_codes[BATCH*512];
__device__ float g_wts[BATCH*3];
__device__ float g_vert[BATCH*99];
// LUT in gather-friendly layout: [b][i(33)][j(33)][k0(32)][dk(2)*4ch] -> 32B blocks
__device__ __align__(32) float g_lut[BATCH*33*33*32*8];

// ---------------- 1) bilinear 1024 -> 256 (fracs are exactly 0.5) ----------
__global__ void resize_kernel(const float* __restrict__ in, float* __restrict__ out){
    int t = blockIdx.x*blockDim.x + threadIdx.x;       // < BATCH*3*256*256
    int ox = t & 255, oy = (t>>8) & 255;
    int pc = t >> 16;                                  // b*3+c plane index
    const float* ip = in + (size_t)pc * HWIN;
    int y0 = 4*oy+1, x0 = 4*ox+1;
    const float* r0 = ip + (size_t)y0*1024 + x0;
    out[t] = 0.25f*(r0[0] + r0[1] + r0[1024] + r0[1025]);
}

// ---- 2) conv3x3 s2 p1 + bias + LeakyReLU(0.2), P pixels/thread (ILP) ------
// grid = dim3(chunksPerPlane, B*Cout); npx must equal gridDim.x*blockDim.x*P
template<int CIN, int HIN, int HOUT, int P>
__global__ void conv_nl(const float* __restrict__ in, float* __restrict__ out,
                        const float* __restrict__ w, const float* __restrict__ bias,
                        int Cout){
    __shared__ float ws[CIN*9];
    const int tid   = threadIdx.x;
    const int plane = blockIdx.y;
    const int co    = plane % Cout;
    const int b     = plane / Cout;
    for (int i = tid; i < CIN*9; i += blockDim.x) ws[i] = w[co*CIN*9 + i];
    __syncthreads();

    const int base = blockIdx.x*blockDim.x*P + tid;
    int iy[P], ix[P];
    float acc[P];
    const float bi = bias[co];
    #pragma unroll
    for (int i = 0; i < P; ++i){
        int p  = base + i*blockDim.x;
        int oy = p / HOUT, ox = p % HOUT;      // HOUT is a power of two -> shifts
        iy[i] = 2*oy - 1; ix[i] = 2*ox - 1;
        acc[i] = bi;
    }
    const float* inb = in + (size_t)b*CIN*HIN*HIN;
    #pragma unroll 2
    for (int ci = 0; ci < CIN; ++ci){
        const float* ip   = inb + ci*HIN*HIN;
        const float* wrow = ws  + ci*9;
        #pragma unroll
        for (int ky = 0; ky < 3; ++ky){
            #pragma unroll
            for (int kx = 0; kx < 3; ++kx){
                const float wv = wrow[ky*3 + kx];
                #pragma unroll
                for (int i = 0; i < P; ++i){
                    int y = iy[i] + ky, x = ix[i] + kx;
                    if ((unsigned)y < (unsigned)HIN && (unsigned)x < (unsigned)HIN)
                        acc[i] += ip[y*HIN + x] * wv;
                }
            }
        }
    }
    float* ob = out + (size_t)plane*HOUT*HOUT;
    #pragma unroll
    for (int i = 0; i < P; ++i){
        float a = acc[i];
        a = a >= 0.f ? a : 0.2f*a;             // LeakyReLU(0.2)
        ob[base + i*blockDim.x] = a;
    }
}

// ---- 2b) InstanceNorm(affine) in-place, one CTA (256 thr) per plane -------
__global__ void inorm(float* __restrict__ x, const float* __restrict__ gamma,
                      const float* __restrict__ beta, int Cout, int npx){
    __shared__ float s1[8], s2[8];
    const int plane = blockIdx.x, tid = threadIdx.x;
    const int co = plane % Cout;
    float* xp = x + (size_t)plane*npx;
    float s = 0.f, q = 0.f;
    for (int i = tid; i < npx; i += 256){ float v = xp[i]; s += v; q += v*v; }
    #pragma unroll
    for (int o = 16; o; o >>= 1){
        s += __shfl_xor_sync(0xffffffffu, s, o);
        q += __shfl_xor_sync(0xffffffffu, q, o);
    }
    if ((tid & 31) == 0){ s1[tid>>5] = s; s2[tid>>5] = q; }
    __syncthreads();
    if (tid < 32){
        float a = tid < 8 ? s1[tid] : 0.f;
        float c = tid < 8 ? s2[tid] : 0.f;
        #pragma unroll
        for (int o = 4; o; o >>= 1){
            a += __shfl_xor_sync(0xffffffffu, a, o);
            c += __shfl_xor_sync(0xffffffffu, c, o);
        }
        if (tid == 0){ s1[0] = a; s2[0] = c; }
    }
    __syncthreads();
    const float inv  = 1.f/(float)npx;
    const float mean = s1[0]*inv;
    const float var  = s2[0]*inv - mean*mean;       // biased variance (jnp.var)
    const float A  = gamma[co]*rsqrtf(var + 1e-5f);
    const float Bc = beta[co] - mean*A;
    for (int i = tid; i < npx; i += 256) xp[i] = xp[i]*A + Bc;
}

// ---- 3) block5: conv(no norm) + LeakyReLU + AdaptiveAvgPool(2) fused ------
// one CTA per (b, co) plane of 8x8; 64 threads; 4 rotating accumulators
__global__ void conv5_pool(const float* __restrict__ in, const float* __restrict__ w,
                           const float* __restrict__ bias, float* __restrict__ codes){
    __shared__ float ws[1152];      // 128*9
    __shared__ float pv[64];
    int tid = threadIdx.x;
    int b  = blockIdx.x >> 7;
    int co = blockIdx.x & 127;
    for (int i = tid; i < 1152; i += 64) ws[i] = w[co*1152 + i];
    __syncthreads();
    const float* inb = in + (size_t)b*128*256;   // 128 ch * 16*16
    int oy = tid >> 3, ox = tid & 7;
    int iy = 2*oy - 1, ix = 2*ox - 1;
    float a0 = bias[co], a1 = 0.f, a2 = 0.f, a3 = 0.f;
    const float* wp = ws;
    const float* ip = inb;
    for (int ci = 0; ci < 128; ci += 2, wp += 18, ip += 512){
        #pragma unroll
        for (int ky = 0; ky < 3; ++ky){
            int y = iy + ky; if ((unsigned)y >= 16u) continue;
            const float* row  = ip + y*16;
            const float* row2 = row + 256;
            #pragma unroll
            for (int kx = 0; kx < 3; ++kx){
                int x = ix + kx; if ((unsigned)x >= 16u) continue;
                float* dst = (kx == 0) ? ((ky&1) ? &a1 : &a0) : ((kx == 1) ? &a2 : &a3);
                *dst += row[x]*wp[ky*3+kx];
                *dst += row2[x]*wp[9+ky*3+kx];
            }
        }
    }
    float acc = (a0 + a1) + (a2 + a3);
    acc = acc >= 0.f ? acc : 0.2f*acc;
    pv[tid] = acc; __syncthreads();
    if (tid < 4){
        int h1 = tid >> 1, w1 = tid & 1;
        float sum = 0.f;
        #pragma unroll
        for (int yy = 0; yy < 4; ++yy)
            #pragma unroll
            for (int xx = 0; xx < 4; ++xx)
                sum += pv[(h1*4+yy)*8 + w1*4+xx];
        codes[b*512 + co*4 + h1*2 + w1] = sum*(1.f/16.f);
    }
}

// ---- 4) FC heads: weights = codes@lw.T+lb ; vertices via softmax+cumsum ---
__global__ void fc_kernel(const float* __restrict__ codes,
                          const float* __restrict__ lw, const float* __restrict__ lb,
                          const float* __restrict__ aw, const float* __restrict__ ab,
                          float* __restrict__ gw, float* __restrict__ gvert,
                          float* __restrict__ ow, float* __restrict__ ov){
    __shared__ float cs[512];
    __shared__ float iv[96];
    int b = blockIdx.x, tid = threadIdx.x;   // 128 threads
    for (int i = tid; i < 512; i += 128) cs[i] = codes[b*512 + i];
    __syncthreads();
    if (tid < 96){
        float acc = ab[tid];
        const float* ar = aw + tid*512;
        for (int k = 0; k < 512; ++k) acc += cs[k]*ar[k];
        iv[tid] = acc;
    } else if (tid < 99){
        int o = tid - 96;
        float acc = lb[o];
        const float* lr = lw + o*512;
        for (int k = 0; k < 512; ++k) acc += cs[k]*lr[k];
        gw[b*3+o] = acc; ow[b*3+o] = acc;
    }
    __syncthreads();
    if (tid < 3){
        const float* x = iv + tid*32;
        float m = x[0];
        for (int i = 1; i < 32; ++i) m = fmaxf(m, x[i]);
        float ssum = 0.f;
        for (int i = 0; i < 32; ++i) ssum += expf(x[i]-m);
        float inv = 1.f/ssum;
        int base = (b*3 + tid)*33;
        gvert[base] = 0.f; ov[base] = 0.f;
        float cum = 0.f;
        for (int i = 0; i < 32; ++i){
            cum += expf(x[i]-m)*inv;
            gvert[base+1+i] = cum; ov[base+1+i] = cum;
        }
    }
}

// ---- 5) combined LUT in pair-duplicated layout ----------------------------
// slot = dk*4 + c ; element (b,i,j,k0,slot)
__global__ void lutgen(const float* __restrict__ gw, const float* __restrict__ bw,
                       float* __restrict__ lut){
    int t = blockIdx.x*blockDim.x + threadIdx.x;   // < BATCH*33*33*32*8
    int slot = t & 7;
    int cc = slot & 3, dk = slot >> 2;
    int k  = (t >> 3) & 31;
    int r  = t >> 8;                               // (b*33+i)*33+j
    int j  = r % 33; r /= 33;
    int i  = r % 33; int b = r / 33;
    float val = 0.f;
    if (cc < 3){
        int row = ((cc*33 + i)*33 + j)*33 + (k + dk);
        const float* br = bw + row*3;
        const float* wv = gw + b*3;
        val = wv[0]*br[0] + wv[1]*br[1] + wv[2]*br[2];
    }
    lut[t] = val;
}

// ---- 6) AiLUT transform: searchsorted + trilerp + clamp -------------------
__device__ __forceinline__ float coord_of(float p, const float* v){
    int lo = 0, hi = 33;              // first idx with v[idx] > p (side='right')
    #pragma unroll
    for (int it = 0; it < 6; ++it){
        if (lo < hi){
            int mid = (lo + hi) >> 1;
            if (v[mid] <= p) lo = mid + 1; else hi = mid;
        }
    }
    int idx = lo < 1 ? 1 : (lo > 32 ? 32 : lo);
    float vl = v[idx-1], vh = v[idx];
    float f = (p - vl)/(vh - vl + 1e-8f);
    float c = (float)(idx-1) + f;
    return fminf(fmaxf(c, 0.f), 32.f);
}

__global__ void transform_kernel(const float* __restrict__ lq, const float* __restrict__ vert,
                                 const float* __restrict__ lut, float* __restrict__ out){
    __shared__ float sv[99];
    int b   = blockIdx.y;
    int tid = threadIdx.x;
    if (tid < 99) sv[tid] = vert[b*99 + tid];
    __syncthreads();
    const float* ib = lq  + (size_t)b*3*HWIN;
    float*       ob = out + (size_t)b*3*HWIN;
    const float* lb = lut + (size_t)b*278784;    // 33*33*32*8
    int base = blockIdx.x*1024 + tid;
    #pragma unroll
    for (int pp = 0; pp < 4; ++pp){
        int n = base + pp*256;
        float r  = ib[n];
        float g  = ib[HWIN + n];
        float bl = ib[2*HWIN + n];
        float cr = coord_of(r,  sv);
        float cg = coord_of(g,  sv + 33);
        float cb = coord_of(bl, sv + 66);
        int i0 = (int)cr; i0 = i0 > 31 ? 31 : i0; float fr = cr - (float)i0;
        int j0 = (int)cg; j0 = j0 > 31 ? 31 : j0; float fg = cg - (float)j0;
        int k0 = (int)cb; k0 = k0 > 31 ? 31 : k0; float fk = cb - (float)k0;
        const float* p00 = lb + ((i0*33 + j0) << 8) + (k0 << 3);
        float w00 = (1.f-fr)*(1.f-fg), w01 = (1.f-fr)*fg;
        float w10 = fr*(1.f-fg),       w11 = fr*fg;
        float a0 = 0.f, a1 = 0.f, a2 = 0.f;
        {   // (i0, j0)
            float4 lo = *(const float4*)p00, hi = *(const float4*)(p00+4);
            a0 += w00*(lo.x + fk*(hi.x-lo.x));
            a1 += w00*(lo.y + fk*(hi.y-lo.y));
            a2 += w00*(lo.z + fk*(hi.z-lo.z));
        }
        {   // (i0, j0+1)
            const float* p = p00 + 256;
            float4 lo = *(const float4*)p, hi = *(const float4*)(p+4);
            a0 += w01*(lo.x + fk*(hi.x-lo.x));
            a1 += w01*(lo.y + fk*(hi.y-lo.y));
            a2 += w01*(lo.z + fk*(hi.z-lo.z));
        }
        {   // (i0+1, j0)
            const float* p = p00 + 33*256;
            float4 lo = *(const float4*)p, hi = *(const float4*)(p+4);
            a0 += w10*(lo.x + fk*(hi.x-lo.x));
            a1 += w10*(lo.y + fk*(hi.y-lo.y));
            a2 += w10*(lo.z + fk*(hi.z-lo.z));
        }
        {   // (i0+1, j0+1)
            const float* p = p00 + 33*256 + 256;
            float4 lo = *(const float4*)p, hi = *(const float4*)(p+4);
            a0 += w11*(lo.x + fk*(hi.x-lo.x));
            a1 += w11*(lo.y + fk*(hi.y-lo.y));
            a2 += w11*(lo.z + fk*(hi.z-lo.z));
        }
        ob[n]          = fminf(fmaxf(a0, 0.f), 1.f);
        ob[HWIN + n]   = fminf(fmaxf(a1, 0.f), 1.f);
        ob[2*HWIN + n] = fminf(fmaxf(a2, 0.f), 1.f);
    }
}

// ---------------------------------------------------------------------------
extern "C" void kernel_launch(void* const* d_in, const int* in_sizes, int n_in,
                              void* d_out, int out_size){
    const float* lq  = (const float*)d_in[0];
    const float* w1  = (const float*)d_in[1];
    const float* b1  = (const float*)d_in[2];
    const float* g1  = (const float*)d_in[3];
    const float* be1 = (const float*)d_in[4];
    const float* w2  = (const float*)d_in[5];
    const float* b2  = (const float*)d_in[6];
    const float* g2  = (const float*)d_in[7];
    const float* be2 = (const float*)d_in[8];
    const float* w3  = (const float*)d_in[9];
    const float* b3  = (const float*)d_in[10];
    const float* g3  = (const float*)d_in[11];
    const float* be3 = (const float*)d_in[12];
    const float* w4  = (const float*)d_in[13];
    const float* b4  = (const float*)d_in[14];
    const float* g4  = (const float*)d_in[15];
    const float* be4 = (const float*)d_in[16];
    const float* w5  = (const float*)d_in[17];
    const float* b5  = (const float*)d_in[18];
    const float* lw  = (const float*)d_in[19];
    const float* lb  = (const float*)d_in[20];
    const float* bw  = (const float*)d_in[21];
    const float* aw  = (const float*)d_in[22];
    const float* ab  = (const float*)d_in[23];
    float* out = (float*)d_out;

    float *x0,*x1,*x2,*x3,*x4,*codes,*wS,*vS,*lutp;
    cudaGetSymbolAddress((void**)&x0,    g_x0);
    cudaGetSymbolAddress((void**)&x1,    g_x1);
    cudaGetSymbolAddress((void**)&x2,    g_x2);
    cudaGetSymbolAddress((void**)&x3,    g_x3);
    cudaGetSymbolAddress((void**)&x4,    g_x4);
    cudaGetSymbolAddress((void**)&codes, g_codes);
    cudaGetSymbolAddress((void**)&wS,    g_wts);
    cudaGetSymbolAddress((void**)&vS,    g_vert);
    cudaGetSymbolAddress((void**)&lutp,  g_lut);

    const size_t OFF_W = (size_t)BATCH*3*HWIN;   // 12,582,912
    const size_t OFF_V = OFF_W + BATCH*3;        // +12

    resize_kernel<<<(BATCH*3*256*256)/256, 256>>>(lq, x0);

    // block1: 3->16, 256->128 (npx=16384 = 16*256*4)
    conv_nl<3,256,128,4><<<dim3(16, BATCH*16), 256>>>(x0, x1, w1, b1, 16);
    inorm<<<BATCH*16, 256>>>(x1, g1, be1, 16, 128*128);
    // block2: 16->32, 128->64 (npx=4096 = 4*256*4)
    conv_nl<16,128,64,4><<<dim3(4, BATCH*32), 256>>>(x1, x2, w2, b2, 32);
    inorm<<<BATCH*32, 256>>>(x2, g2, be2, 32, 64*64);
    // block3: 32->64, 64->32 (npx=1024 = 1*256*4)
    conv_nl<32,64,32,4><<<dim3(1, BATCH*64), 256>>>(x2, x3, w3, b3, 64);
    inorm<<<BATCH*64, 256>>>(x3, g3, be3, 64, 32*32);
    // block4: 64->128, 32->16 (npx=256 = 1*64*4)
    conv_nl<64,32,16,4><<<dim3(1, BATCH*128), 64>>>(x3, x4, w4, b4, 128);
    inorm<<<BATCH*128, 256>>>(x4, g4, be4, 128, 16*16);

    conv5_pool<<<BATCH*128, 64>>>(x4, w5, b5, codes);
    fc_kernel<<<BATCH, 128>>>(codes, lw, lb, aw, ab, wS, vS, out + OFF_W, out + OFF_V);
    lutgen<<<(BATCH*33*33*32*8)/256, 256>>>(wS, bw, lutp);
    transform_kernel<<<dim3(1024, BATCH), 256>>>(lq, vS, lutp, out);
}

// round 7
// speedup vs baseline: 1.7329x; 1.3795x over previous
#include <cuda_runtime.h>
#include <math.h>

#define BATCH 4
#define HWIN (1024*1024)

// ---------------- scratch (static device memory, no allocs) ----------------
__device__ float g_x0[BATCH*3*256*256];       // resized input
__device__ float g_x1[BATCH*16*128*128];
__device__ float g_x2[BATCH*32*64*64];
__device__ float g_x3[BATCH*64*32*32];
__device__ float g_x4[BATCH*128*16*16];
__device__ float g_codes[BATCH*512];
__device__ float g_wts[BATCH*3];
__device__ float g_vert[BATCH*99];
// LUT in gather-friendly layout: [b][i(33)][j(33)][k0(32)][dk(2)*4ch] -> 32B blocks
__device__ __align__(32) float g_lut[BATCH*33*33*32*8];

// ---------------- 1) bilinear 1024 -> 256 (fracs are exactly 0.5) ----------
__global__ void resize_kernel(const float* __restrict__ in, float* __restrict__ out){
    int t = blockIdx.x*blockDim.x + threadIdx.x;       // < BATCH*3*256*256
    int ox = t & 255, oy = (t>>8) & 255;
    int pc = t >> 16;                                  // b*3+c plane index
    const float* ip = in + (size_t)pc * HWIN;
    int y0 = 4*oy+1, x0 = 4*ox+1;
    const float* r0 = ip + (size_t)y0*1024 + x0;
    out[t] = 0.25f*(r0[0] + r0[1] + r0[1024] + r0[1025]);
}

// ---- 2) smem-tiled conv3x3 s2 p1 + bias + LeakyReLU(0.2) -----------------
// CTA: TYxTX output tile x COB cout channels. Thread: 4 x-pixels x PCO cout.
// grid: x = (HOUT/TY)*(HOUT/TX) tiles, y = Cout/COB, z = batch
template<int CIN, int COB, int HIN, int HOUT, int TY, int TX, int PCO>
__global__ void conv_tile(const float* __restrict__ in, float* __restrict__ out,
                          const float* __restrict__ w, const float* __restrict__ bias,
                          int Cout){
    constexpr int PX   = 4;
    constexpr int NCO  = COB/PCO;
    constexpr int NPXG = (TY*TX)/PX;
    constexpr int NTHR = NCO*NPXG;
    constexpr int IR   = 2*TY+1;
    constexpr int IC   = 2*TX+4;          // padded to mult of 4
    constexpr int INSZ = CIN*IR*IC;
    constexpr int WSZ  = CIN*3*COB*4;     // [ci][ky][co][kx pad4]
    extern __shared__ float sm[];
    float* sIn = sm;
    float* sW  = sm + INSZ;

    const int tid    = threadIdx.x;
    const int tilesX = HOUT/TX;
    const int ty0 = (blockIdx.x / tilesX)*TY;
    const int tx0 = (blockIdx.x % tilesX)*TX;
    const int co0 = blockIdx.y*COB;
    const int b   = blockIdx.z;

    // weights -> smem in [ci][ky][co][kx(4)] layout
    for (int i = tid; i < WSZ; i += NTHR){
        int kx = i & 3;
        int co = (i >> 2) % COB;
        int t  = (i >> 2) / COB;          // ci*3+ky
        int ky = t % 3, ci = t / 3;
        sW[i] = (kx < 3) ? w[(size_t)(co0+co)*CIN*9 + ci*9 + ky*3 + kx] : 0.f;
    }
    // input tile -> smem, zero-padded (pad=1 and row pad)
    const float* inb = in + (size_t)b*CIN*HIN*HIN;
    for (int i = tid; i < INSZ; i += NTHR){
        int rx = i % IC;
        int ry = (i / IC) % IR;
        int ci = i / (IC*IR);
        int y = 2*ty0 - 1 + ry;
        int x = 2*tx0 - 1 + rx;
        float v = 0.f;
        if (rx < 2*TX+1 && (unsigned)y < (unsigned)HIN && (unsigned)x < (unsigned)HIN)
            v = inb[(size_t)ci*HIN*HIN + y*HIN + x];
        sIn[i] = v;
    }
    __syncthreads();

    const int tco = tid % NCO;
    const int tpx = tid / NCO;
    const int gy  = tpx / (TX/PX);
    const int gx  = (tpx % (TX/PX))*PX;

    float acc[PCO][PX];
    #pragma unroll
    for (int c = 0; c < PCO; ++c){
        float bv = bias[co0 + tco*PCO + c];
        #pragma unroll
        for (int p = 0; p < PX; ++p) acc[c][p] = bv;
    }

    #pragma unroll 2
    for (int ci = 0; ci < CIN; ++ci){
        const float* ip = sIn + ci*IR*IC + (2*gy)*IC + 2*gx;
        const float* wp = sW  + (ci*3*COB + tco*PCO)*4;
        #pragma unroll
        for (int ky = 0; ky < 3; ++ky){
            float4 ra = *(const float4*)(ip + ky*IC);
            float4 rb = *(const float4*)(ip + ky*IC + 4);
            float  r8 = ip[ky*IC + 8];
            float r0=ra.x, r1=ra.y, r2=ra.z, r3=ra.w;
            float r4=rb.x, r5=rb.y, r6=rb.z, r7=rb.w;
            #pragma unroll
            for (int c = 0; c < PCO; ++c){
                float4 wv = *(const float4*)(wp + (ky*COB + c)*4);
                acc[c][0] += r0*wv.x; acc[c][0] += r1*wv.y; acc[c][0] += r2*wv.z;
                acc[c][1] += r2*wv.x; acc[c][1] += r3*wv.y; acc[c][1] += r4*wv.z;
                acc[c][2] += r4*wv.x; acc[c][2] += r5*wv.y; acc[c][2] += r6*wv.z;
                acc[c][3] += r6*wv.x; acc[c][3] += r7*wv.y; acc[c][3] += r8*wv.z;
            }
        }
    }
    #pragma unroll
    for (int c = 0; c < PCO; ++c){
        int co = co0 + tco*PCO + c;
        float* ob = out + (((size_t)b*Cout + co)*HOUT + (ty0+gy))*HOUT + tx0 + gx;
        float4 v;
        v.x = acc[c][0] >= 0.f ? acc[c][0] : 0.2f*acc[c][0];
        v.y = acc[c][1] >= 0.f ? acc[c][1] : 0.2f*acc[c][1];
        v.z = acc[c][2] >= 0.f ? acc[c][2] : 0.2f*acc[c][2];
        v.w = acc[c][3] >= 0.f ? acc[c][3] : 0.2f*acc[c][3];
        *(float4*)ob = v;
    }
}

// ---- 2b) InstanceNorm(affine) in-place, one CTA (256 thr) per plane -------
__global__ void inorm(float* __restrict__ x, const float* __restrict__ gamma,
                      const float* __restrict__ beta, int Cout, int npx){
    __shared__ float s1[8], s2[8];
    const int plane = blockIdx.x, tid = threadIdx.x;
    const int co = plane % Cout;
    float* xp = x + (size_t)plane*npx;
    float s = 0.f, q = 0.f;
    for (int i = tid; i < npx; i += 256){ float v = xp[i]; s += v; q += v*v; }
    #pragma unroll
    for (int o = 16; o; o >>= 1){
        s += __shfl_xor_sync(0xffffffffu, s, o);
        q += __shfl_xor_sync(0xffffffffu, q, o);
    }
    if ((tid & 31) == 0){ s1[tid>>5] = s; s2[tid>>5] = q; }
    __syncthreads();
    if (tid < 32){
        float a = tid < 8 ? s1[tid] : 0.f;
        float c = tid < 8 ? s2[tid] : 0.f;
        #pragma unroll
        for (int o = 4; o; o >>= 1){
            a += __shfl_xor_sync(0xffffffffu, a, o);
            c += __shfl_xor_sync(0xffffffffu, c, o);
        }
        if (tid == 0){ s1[0] = a; s2[0] = c; }
    }
    __syncthreads();
    const float inv  = 1.f/(float)npx;
    const float mean = s1[0]*inv;
    const float var  = s2[0]*inv - mean*mean;       // biased variance (jnp.var)
    const float A  = gamma[co]*rsqrtf(var + 1e-5f);
    const float Bc = beta[co] - mean*A;
    for (int i = tid; i < npx; i += 256) xp[i] = xp[i]*A + Bc;
}

// ---- 3) block5: conv(no norm) + LeakyReLU + AdaptiveAvgPool(2) fused ------
// one CTA per (b, co); 128 threads: 64 px x 2 ci-halves
__global__ void conv5_pool(const float* __restrict__ in, const float* __restrict__ w,
                           const float* __restrict__ bias, float* __restrict__ codes){
    __shared__ float ws[1152];      // 128*9
    __shared__ float pv[128];
    int tid = threadIdx.x;          // 128
    int b  = blockIdx.x >> 7;
    int co = blockIdx.x & 127;
    for (int i = tid; i < 1152; i += 128) ws[i] = w[co*1152 + i];
    __syncthreads();
    int half = tid >> 6;            // ci half
    int px   = tid & 63;
    int oy = px >> 3, ox = px & 7;
    int iy = 2*oy - 1, ix = 2*ox - 1;
    float a0 = half ? 0.f : bias[co], a1 = 0.f, a2 = 0.f, a3 = 0.f;
    const float* ip = in + (size_t)b*128*256 + half*64*256;
    const float* wp = ws + half*64*9;
    for (int ci = 0; ci < 64; ci += 2, wp += 18, ip += 512){
        #pragma unroll
        for (int ky = 0; ky < 3; ++ky){
            int y = iy + ky; if ((unsigned)y >= 16u) continue;
            const float* row  = ip + y*16;
            const float* row2 = row + 256;
            #pragma unroll
            for (int kx = 0; kx < 3; ++kx){
                int x = ix + kx; if ((unsigned)x >= 16u) continue;
                float* dst = (kx == 0) ? ((ky&1) ? &a1 : &a0) : ((kx == 1) ? &a2 : &a3);
                *dst += row[x]*wp[ky*3+kx];
                *dst += row2[x]*wp[9+ky*3+kx];
            }
        }
    }
    pv[tid] = (a0 + a1) + (a2 + a3);
    __syncthreads();
    if (tid < 64){
        float v = pv[tid] + pv[tid+64];
        v = v >= 0.f ? v : 0.2f*v;
        pv[tid] = v;
    }
    __syncthreads();
    if (tid < 4){
        int h1 = tid >> 1, w1 = tid & 1;
        float sum = 0.f;
        #pragma unroll
        for (int yy = 0; yy < 4; ++yy)
            #pragma unroll
            for (int xx = 0; xx < 4; ++xx)
                sum += pv[(h1*4+yy)*8 + w1*4+xx];
        codes[b*512 + co*4 + h1*2 + w1] = sum*(1.f/16.f);
    }
}

// ---- 4) FC heads: weights = codes@lw.T+lb ; vertices via softmax+cumsum ---
__global__ void fc_kernel(const float* __restrict__ codes,
                          const float* __restrict__ lw, const float* __restrict__ lb,
                          const float* __restrict__ aw, const float* __restrict__ ab,
                          float* __restrict__ gw, float* __restrict__ gvert,
                          float* __restrict__ ow, float* __restrict__ ov){
    __shared__ float cs[512];
    __shared__ float iv[96];
    int b = blockIdx.x, tid = threadIdx.x;   // 128 threads
    for (int i = tid; i < 512; i += 128) cs[i] = codes[b*512 + i];
    __syncthreads();
    if (tid < 96){
        float acc = ab[tid];
        const float* ar = aw + tid*512;
        for (int k = 0; k < 512; ++k) acc += cs[k]*ar[k];
        iv[tid] = acc;
    } else if (tid < 99){
        int o = tid - 96;
        float acc = lb[o];
        const float* lr = lw + o*512;
        for (int k = 0; k < 512; ++k) acc += cs[k]*lr[k];
        gw[b*3+o] = acc; ow[b*3+o] = acc;
    }
    __syncthreads();
    if (tid < 3){
        const float* x = iv + tid*32;
        float m = x[0];
        for (int i = 1; i < 32; ++i) m = fmaxf(m, x[i]);
        float ssum = 0.f;
        for (int i = 0; i < 32; ++i) ssum += expf(x[i]-m);
        float inv = 1.f/ssum;
        int base = (b*3 + tid)*33;
        gvert[base] = 0.f; ov[base] = 0.f;
        float cum = 0.f;
        for (int i = 0; i < 32; ++i){
            cum += expf(x[i]-m)*inv;
            gvert[base+1+i] = cum; ov[base+1+i] = cum;
        }
    }
}

// ---- 5) combined LUT in pair-duplicated layout ----------------------------
__global__ void lutgen(const float* __restrict__ gw, const float* __restrict__ bw,
                       float* __restrict__ lut){
    int t = blockIdx.x*blockDim.x + threadIdx.x;   // < BATCH*33*33*32*8
    int slot = t & 7;
    int cc = slot & 3, dk = slot >> 2;
    int k  = (t >> 3) & 31;
    int r  = t >> 8;                               // (b*33+i)*33+j
    int j  = r % 33; r /= 33;
    int i  = r % 33; int b = r / 33;
    float val = 0.f;
    if (cc < 3){
        int row = ((cc*33 + i)*33 + j)*33 + (k + dk);
        const float* br = bw + row*3;
        const float* wv = gw + b*3;
        val = wv[0]*br[0] + wv[1]*br[1] + wv[2]*br[2];
    }
    lut[t] = val;
}

// ---- 6) AiLUT transform: searchsorted + trilerp + clamp -------------------
__device__ __forceinline__ float coord_of(float p, const float* v){
    int lo = 0, hi = 33;              // first idx with v[idx] > p (side='right')
    #pragma unroll
    for (int it = 0; it < 6; ++it){
        if (lo < hi){
            int mid = (lo + hi) >> 1;
            if (v[mid] <= p) lo = mid + 1; else hi = mid;
        }
    }
    int idx = lo < 1 ? 1 : (lo > 32 ? 32 : lo);
    float vl = v[idx-1], vh = v[idx];
    float f = (p - vl)/(vh - vl + 1e-8f);
    float c = (float)(idx-1) + f;
    return fminf(fmaxf(c, 0.f), 32.f);
}

__global__ void transform_kernel(const float* __restrict__ lq, const float* __restrict__ vert,
                                 const float* __restrict__ lut, float* __restrict__ out){
    __shared__ float sv[99];
    int b   = blockIdx.y;
    int tid = threadIdx.x;
    if (tid < 99) sv[tid] = vert[b*99 + tid];
    __syncthreads();
    const float* ib = lq  + (size_t)b*3*HWIN;
    float*       ob = out + (size_t)b*3*HWIN;
    const float* lb = lut + (size_t)b*278784;    // 33*33*32*8
    int base = blockIdx.x*1024 + tid;
    #pragma unroll
    for (int pp = 0; pp < 4; ++pp){
        int n = base + pp*256;
        float r  = ib[n];
        float g  = ib[HWIN + n];
        float bl = ib[2*HWIN + n];
        float cr = coord_of(r,  sv);
        float cg = coord_of(g,  sv + 33);
        float cb = coord_of(bl, sv + 66);
        int i0 = (int)cr; i0 = i0 > 31 ? 31 : i0; float fr = cr - (float)i0;
        int j0 = (int)cg; j0 = j0 > 31 ? 31 : j0; float fg = cg - (float)j0;
        int k0 = (int)cb; k0 = k0 > 31 ? 31 : k0; float fk = cb - (float)k0;
        const float* p00 = lb + ((i0*33 + j0) << 8) + (k0 << 3);
        float w00 = (1.f-fr)*(1.f-fg), w01 = (1.f-fr)*fg;
        float w10 = fr*(1.f-fg),       w11 = fr*fg;
        float a0 = 0.f, a1 = 0.f, a2 = 0.f;
        {   // (i0, j0)
            float4 lo = *(const float4*)p00, hi = *(const float4*)(p00+4);
            a0 += w00*(lo.x + fk*(hi.x-lo.x));
            a1 += w00*(lo.y + fk*(hi.y-lo.y));
            a2 += w00*(lo.z + fk*(hi.z-lo.z));
        }
        {   // (i0, j0+1)
            const float* p = p00 + 256;
            float4 lo = *(const float4*)p, hi = *(const float4*)(p+4);
            a0 += w01*(lo.x + fk*(hi.x-lo.x));
            a1 += w01*(lo.y + fk*(hi.y-lo.y));
            a2 += w01*(lo.z + fk*(hi.z-lo.z));
        }
        {   // (i0+1, j0)
            const float* p = p00 + 33*256;
            float4 lo = *(const float4*)p, hi = *(const float4*)(p+4);
            a0 += w10*(lo.x + fk*(hi.x-lo.x));
            a1 += w10*(lo.y + fk*(hi.y-lo.y));
            a2 += w10*(lo.z + fk*(hi.z-lo.z));
        }
        {   // (i0+1, j0+1)
            const float* p = p00 + 33*256 + 256;
            float4 lo = *(const float4*)p, hi = *(const float4*)(p+4);
            a0 += w11*(lo.x + fk*(hi.x-lo.x));
            a1 += w11*(lo.y + fk*(hi.y-lo.y));
            a2 += w11*(lo.z + fk*(hi.z-lo.z));
        }
        ob[n]          = fminf(fmaxf(a0, 0.f), 1.f);
        ob[HWIN + n]   = fminf(fmaxf(a1, 0.f), 1.f);
        ob[2*HWIN + n] = fminf(fmaxf(a2, 0.f), 1.f);
    }
}

// ---------------------------------------------------------------------------
extern "C" void kernel_launch(void* const* d_in, const int* in_sizes, int n_in,
                              void* d_out, int out_size){
    const float* lq  = (const float*)d_in[0];
    const float* w1  = (const float*)d_in[1];
    const float* b1  = (const float*)d_in[2];
    const float* g1  = (const float*)d_in[3];
    const float* be1 = (const float*)d_in[4];
    const float* w2  = (const float*)d_in[5];
    const float* b2  = (const float*)d_in[6];
    const float* g2  = (const float*)d_in[7];
    const float* be2 = (const float*)d_in[8];
    const float* w3  = (const float*)d_in[9];
    const float* b3  = (const float*)d_in[10];
    const float* g3  = (const float*)d_in[11];
    const float* be3 = (const float*)d_in[12];
    const float* w4  = (const float*)d_in[13];
    const float* b4  = (const float*)d_in[14];
    const float* g4  = (const float*)d_in[15];
    const float* be4 = (const float*)d_in[16];
    const float* w5  = (const float*)d_in[17];
    const float* b5  = (const float*)d_in[18];
    const float* lw  = (const float*)d_in[19];
    const float* lb  = (const float*)d_in[20];
    const float* bw  = (const float*)d_in[21];
    const float* aw  = (const float*)d_in[22];
    const float* ab  = (const float*)d_in[23];
    float* out = (float*)d_out;

    float *x0,*x1,*x2,*x3,*x4,*codes,*wS,*vS,*lutp;
    cudaGetSymbolAddress((void**)&x0,    g_x0);
    cudaGetSymbolAddress((void**)&x1,    g_x1);
    cudaGetSymbolAddress((void**)&x2,    g_x2);
    cudaGetSymbolAddress((void**)&x3,    g_x3);
    cudaGetSymbolAddress((void**)&x4,    g_x4);
    cudaGetSymbolAddress((void**)&codes, g_codes);
    cudaGetSymbolAddress((void**)&wS,    g_wts);
    cudaGetSymbolAddress((void**)&vS,    g_vert);
    cudaGetSymbolAddress((void**)&lutp,  g_lut);

    const size_t OFF_W = (size_t)BATCH*3*HWIN;   // 12,582,912
    const size_t OFF_V = OFF_W + BATCH*3;        // +12

    // dynamic smem sizes (floats): CIN*(2TY+1)*(2TX+4) + CIN*3*COB*4
    const int SM1 = (3*9*36  + 3*3*16*4)  * 4;   //  6192 B
    const int SM2 = (16*9*20 + 16*3*32*4) * 4;   // 36096 B
    const int SM3 = (32*9*20 + 32*3*32*4) * 4;   // 72192 B
    const int SM4 = (64*9*20 + 64*3*32*4) * 4;   // 144384 B
    cudaFuncSetAttribute((const void*)conv_tile<32,32,64,32,4,8,2>,
                         cudaFuncAttributeMaxDynamicSharedMemorySize, SM3);
    cudaFuncSetAttribute((const void*)conv_tile<64,32,32,16,4,8,2>,
                         cudaFuncAttributeMaxDynamicSharedMemorySize, SM4);

    resize_kernel<<<(BATCH*3*256*256)/256, 256>>>(lq, x0);

    // block1: 3->16, 256->128, tile 4x16
    conv_tile<3,16,256,128,4,16,2><<<dim3(32*8, 1, BATCH), 128, SM1>>>(x0, x1, w1, b1, 16);
    inorm<<<BATCH*16, 256>>>(x1, g1, be1, 16, 128*128);
    // block2: 16->32, 128->64, tile 4x8
    conv_tile<16,32,128,64,4,8,2><<<dim3(16*8, 1, BATCH), 128, SM2>>>(x1, x2, w2, b2, 32);
    inorm<<<BATCH*32, 256>>>(x2, g2, be2, 32, 64*64);
    // block3: 32->64, 64->32, tile 4x8, 2 co-blocks
    conv_tile<32,32,64,32,4,8,2><<<dim3(8*4, 2, BATCH), 128, SM3>>>(x2, x3, w3, b3, 64);
    inorm<<<BATCH*64, 256>>>(x3, g3, be3, 64, 32*32);
    // block4: 64->128, 32->16, tile 4x8, 4 co-blocks
    conv_tile<64,32,32,16,4,8,2><<<dim3(4*2, 4, BATCH), 128, SM4>>>(x3, x4, w4, b4, 128);
    inorm<<<BATCH*128, 256>>>(x4, g4, be4, 128, 16*16);

    conv5_pool<<<BATCH*128, 128>>>(x4, w5, b5, codes);
    fc_kernel<<<BATCH, 128>>>(codes, lw, lb, aw, ab, wS, vS, out + OFF_W, out + OFF_V);
    lutgen<<<(BATCH*33*33*32*8)/256, 256>>>(wS, bw, lutp);
    transform_kernel<<<dim3(1024, BATCH), 256>>>(lq, vS, lutp, out);
}

// round 9
// speedup vs baseline: 1.9061x; 1.1000x over previous
#include <cuda_runtime.h>
#include <cuda_fp16.h>
#include <math.h>

#define BATCH 4
#define HWIN (1024*1024)

// ---------------- scratch (static device memory, no allocs) ----------------
__device__ float g_x0[BATCH*3*256*256];       // resized input
__device__ float g_x1[BATCH*16*128*128];
__device__ float g_x2[BATCH*32*64*64];
__device__ float g_x3[BATCH*64*32*32];
__device__ float g_x4[BATCH*128*16*16];
__device__ float g_codes[BATCH*512];
__device__ float g_wts[BATCH*3];
__device__ float g_vert[BATCH*99];
__device__ unsigned char g_tab[BATCH*3*256];  // searchsorted accel table
// fp16 LUT, packed: [b][i(33)][j0(32)][k0(32)][dj(2)][dk(2)][ch(4)] -> 32B/block
__device__ __align__(32) __half g_lut[BATCH*33*32*32*16];

// ---------------- 1) bilinear 1024 -> 256 (fracs are exactly 0.5) ----------
__global__ void resize_kernel(const float* __restrict__ in, float* __restrict__ out){
    int t = blockIdx.x*blockDim.x + threadIdx.x;       // < BATCH*3*256*256
    int ox = t & 255, oy = (t>>8) & 255;
    int pc = t >> 16;                                  // b*3+c plane index
    const float* ip = in + (size_t)pc * HWIN;
    int y0 = 4*oy+1, x0 = 4*ox+1;
    const float* r0 = ip + (size_t)y0*1024 + x0;
    out[t] = 0.25f*(r0[0] + r0[1] + r0[1024] + r0[1025]);
}

// ---- 2) smem-tiled conv3x3 s2 p1 + bias + LeakyReLU(0.2) -----------------
template<int CIN, int COB, int HIN, int HOUT, int TY, int TX, int PCO>
__global__ void conv_tile(const float* __restrict__ in, float* __restrict__ out,
                          const float* __restrict__ w, const float* __restrict__ bias,
                          int Cout){
    constexpr int PX   = 4;
    constexpr int NCO  = COB/PCO;
    constexpr int NPXG = (TY*TX)/PX;
    constexpr int NTHR = NCO*NPXG;
    constexpr int IR   = 2*TY+1;
    constexpr int IC   = 2*TX+4;          // padded to mult of 4
    constexpr int INSZ = CIN*IR*IC;
    constexpr int WSZ  = CIN*3*COB*4;     // [ci][ky][co][kx pad4]
    extern __shared__ float sm[];
    float* sIn = sm;
    float* sW  = sm + INSZ;

    const int tid    = threadIdx.x;
    const int tilesX = HOUT/TX;
    const int ty0 = (blockIdx.x / tilesX)*TY;
    const int tx0 = (blockIdx.x % tilesX)*TX;
    const int co0 = blockIdx.y*COB;
    const int b   = blockIdx.z;

    for (int i = tid; i < WSZ; i += NTHR){
        int kx = i & 3;
        int co = (i >> 2) % COB;
        int t  = (i >> 2) / COB;          // ci*3+ky
        int ky = t % 3, ci = t / 3;
        sW[i] = (kx < 3) ? w[(size_t)(co0+co)*CIN*9 + ci*9 + ky*3 + kx] : 0.f;
    }
    const float* inb = in + (size_t)b*CIN*HIN*HIN;
    for (int i = tid; i < INSZ; i += NTHR){
        int rx = i % IC;
        int ry = (i / IC) % IR;
        int ci = i / (IC*IR);
        int y = 2*ty0 - 1 + ry;
        int x = 2*tx0 - 1 + rx;
        float v = 0.f;
        if (rx < 2*TX+1 && (unsigned)y < (unsigned)HIN && (unsigned)x < (unsigned)HIN)
            v = inb[(size_t)ci*HIN*HIN + y*HIN + x];
        sIn[i] = v;
    }
    __syncthreads();

    const int tco = tid % NCO;
    const int tpx = tid / NCO;
    const int gy  = tpx / (TX/PX);
    const int gx  = (tpx % (TX/PX))*PX;

    float acc[PCO][PX];
    #pragma unroll
    for (int c = 0; c < PCO; ++c){
        float bv = bias[co0 + tco*PCO + c];
        #pragma unroll
        for (int p = 0; p < PX; ++p) acc[c][p] = bv;
    }

    #pragma unroll 2
    for (int ci = 0; ci < CIN; ++ci){
        const float* ip = sIn + ci*IR*IC + (2*gy)*IC + 2*gx;
        const float* wp = sW  + (ci*3*COB + tco*PCO)*4;
        #pragma unroll
        for (int ky = 0; ky < 3; ++ky){
            float4 ra = *(const float4*)(ip + ky*IC);
            float4 rb = *(const float4*)(ip + ky*IC + 4);
            float  r8 = ip[ky*IC + 8];
            float r0=ra.x, r1=ra.y, r2=ra.z, r3=ra.w;
            float r4=rb.x, r5=rb.y, r6=rb.z, r7=rb.w;
            #pragma unroll
            for (int c = 0; c < PCO; ++c){
                float4 wv = *(const float4*)(wp + (ky*COB + c)*4);
                acc[c][0] += r0*wv.x; acc[c][0] += r1*wv.y; acc[c][0] += r2*wv.z;
                acc[c][1] += r2*wv.x; acc[c][1] += r3*wv.y; acc[c][1] += r4*wv.z;
                acc[c][2] += r4*wv.x; acc[c][2] += r5*wv.y; acc[c][2] += r6*wv.z;
                acc[c][3] += r6*wv.x; acc[c][3] += r7*wv.y; acc[c][3] += r8*wv.z;
            }
        }
    }
    #pragma unroll
    for (int c = 0; c < PCO; ++c){
        int co = co0 + tco*PCO + c;
        float* ob = out + (((size_t)b*Cout + co)*HOUT + (ty0+gy))*HOUT + tx0 + gx;
        float4 v;
        v.x = acc[c][0] >= 0.f ? acc[c][0] : 0.2f*acc[c][0];
        v.y = acc[c][1] >= 0.f ? acc[c][1] : 0.2f*acc[c][1];
        v.z = acc[c][2] >= 0.f ? acc[c][2] : 0.2f*acc[c][2];
        v.w = acc[c][3] >= 0.f ? acc[c][3] : 0.2f*acc[c][3];
        *(float4*)ob = v;
    }
}

// ---- 2b) InstanceNorm(affine) in-place, one CTA (256 thr) per plane -------
__global__ void inorm(float* __restrict__ x, const float* __restrict__ gamma,
                      const float* __restrict__ beta, int Cout, int npx){
    __shared__ float s1[8], s2[8];
    const int plane = blockIdx.x, tid = threadIdx.x;
    const int co = plane % Cout;
    float* xp = x + (size_t)plane*npx;
    float s = 0.f, q = 0.f;
    for (int i = tid; i < npx; i += 256){ float v = xp[i]; s += v; q += v*v; }
    #pragma unroll
    for (int o = 16; o; o >>= 1){
        s += __shfl_xor_sync(0xffffffffu, s, o);
        q += __shfl_xor_sync(0xffffffffu, q, o);
    }
    if ((tid & 31) == 0){ s1[tid>>5] = s; s2[tid>>5] = q; }
    __syncthreads();
    if (tid < 32){
        float a = tid < 8 ? s1[tid] : 0.f;
        float c = tid < 8 ? s2[tid] : 0.f;
        #pragma unroll
        for (int o = 4; o; o >>= 1){
            a += __shfl_xor_sync(0xffffffffu, a, o);
            c += __shfl_xor_sync(0xffffffffu, c, o);
        }
        if (tid == 0){ s1[0] = a; s2[0] = c; }
    }
    __syncthreads();
    const float inv  = 1.f/(float)npx;
    const float mean = s1[0]*inv;
    const float var  = s2[0]*inv - mean*mean;       // biased variance (jnp.var)
    const float A  = gamma[co]*rsqrtf(var + 1e-5f);
    const float Bc = beta[co] - mean*A;
    for (int i = tid; i < npx; i += 256) xp[i] = xp[i]*A + Bc;
}

// ---- 3) block5: conv(no norm) + LeakyReLU + AdaptiveAvgPool(2) fused ------
__global__ void conv5_pool(const float* __restrict__ in, const float* __restrict__ w,
                           const float* __restrict__ bias, float* __restrict__ codes){
    __shared__ float ws[1152];      // 128*9
    __shared__ float pv[128];
    int tid = threadIdx.x;          // 128
    int b  = blockIdx.x >> 7;
    int co = blockIdx.x & 127;
    for (int i = tid; i < 1152; i += 128) ws[i] = w[co*1152 + i];
    __syncthreads();
    int half = tid >> 6;            // ci half
    int px   = tid & 63;
    int oy = px >> 3, ox = px & 7;
    int iy = 2*oy - 1, ix = 2*ox - 1;
    float a0 = half ? 0.f : bias[co], a1 = 0.f, a2 = 0.f, a3 = 0.f;
    const float* ip = in + (size_t)b*128*256 + half*64*256;
    const float* wp = ws + half*64*9;
    for (int ci = 0; ci < 64; ci += 2, wp += 18, ip += 512){
        #pragma unroll
        for (int ky = 0; ky < 3; ++ky){
            int y = iy + ky; if ((unsigned)y >= 16u) continue;
            const float* row  = ip + y*16;
            const float* row2 = row + 256;
            #pragma unroll
            for (int kx = 0; kx < 3; ++kx){
                int x = ix + kx; if ((unsigned)x >= 16u) continue;
                float* dst = (kx == 0) ? ((ky&1) ? &a1 : &a0) : ((kx == 1) ? &a2 : &a3);
                *dst += row[x]*wp[ky*3+kx];
                *dst += row2[x]*wp[9+ky*3+kx];
            }
        }
    }
    pv[tid] = (a0 + a1) + (a2 + a3);
    __syncthreads();
    if (tid < 64){
        float v = pv[tid] + pv[tid+64];
        v = v >= 0.f ? v : 0.2f*v;
        pv[tid] = v;
    }
    __syncthreads();
    if (tid < 4){
        int h1 = tid >> 1, w1 = tid & 1;
        float sum = 0.f;
        #pragma unroll
        for (int yy = 0; yy < 4; ++yy)
            #pragma unroll
            for (int xx = 0; xx < 4; ++xx)
                sum += pv[(h1*4+yy)*8 + w1*4+xx];
        codes[b*512 + co*4 + h1*2 + w1] = sum*(1.f/16.f);
    }
}

// ---- 4) FC heads + searchsorted acceleration table ------------------------
__global__ void fc_kernel(const float* __restrict__ codes,
                          const float* __restrict__ lw, const float* __restrict__ lb,
                          const float* __restrict__ aw, const float* __restrict__ ab,
                          float* __restrict__ gw, float* __restrict__ gvert,
                          unsigned char* __restrict__ gtab,
                          float* __restrict__ ow, float* __restrict__ ov){
    __shared__ float cs[512];
    __shared__ float iv[96];
    __shared__ float vsm[99];
    int b = blockIdx.x, tid = threadIdx.x;   // 128 threads
    for (int i = tid; i < 512; i += 128) cs[i] = codes[b*512 + i];
    __syncthreads();
    if (tid < 96){
        float acc = ab[tid];
        const float* ar = aw + tid*512;
        for (int k = 0; k < 512; ++k) acc += cs[k]*ar[k];
        iv[tid] = acc;
    } else if (tid < 99){
        int o = tid - 96;
        float acc = lb[o];
        const float* lr = lw + o*512;
        for (int k = 0; k < 512; ++k) acc += cs[k]*lr[k];
        gw[b*3+o] = acc; ow[b*3+o] = acc;
    }
    __syncthreads();
    if (tid < 3){
        const float* x = iv + tid*32;
        float m = x[0];
        for (int i = 1; i < 32; ++i) m = fmaxf(m, x[i]);
        float ssum = 0.f;
        for (int i = 0; i < 32; ++i) ssum += expf(x[i]-m);
        float inv = 1.f/ssum;
        int base = (b*3 + tid)*33;
        gvert[base] = 0.f; ov[base] = 0.f; vsm[tid*33] = 0.f;
        float cum = 0.f;
        for (int i = 0; i < 32; ++i){
            cum += expf(x[i]-m)*inv;
            gvert[base+1+i] = cum; ov[base+1+i] = cum; vsm[tid*33+1+i] = cum;
        }
    }
    __syncthreads();
    // accel table: tab[c][m] = first idx in [1,32] with v[idx] > m/256 (clipped)
    for (int e = tid; e < 3*256; e += 128){
        int c = e >> 8, m = e & 255;
        float p = (float)m * (1.f/256.f);
        const float* v = vsm + c*33;
        int idx = 1;
        while (idx < 32 && v[idx] <= p) ++idx;
        gtab[b*768 + e] = (unsigned char)idx;
    }
}

// ---- 5) fp16 packed LUT: [b][i][j0][k0][dj][dk][ch] -----------------------
__global__ void lutgen(const float* __restrict__ gw, const float* __restrict__ bw,
                       __half* __restrict__ lut){
    int t = blockIdx.x*blockDim.x + threadIdx.x;   // < BATCH*33*32*32*16
    int slot = t & 15;
    int cc = slot & 3, dk = (slot >> 2) & 1, dj = slot >> 3;
    int k0 = (t >> 4) & 31;
    int j0 = (t >> 9) & 31;
    int r  = t >> 14;
    int i  = r % 33, b = r / 33;
    float val = 0.f;
    if (cc < 3){
        int row = ((cc*33 + i)*33 + (j0+dj))*33 + (k0+dk);
        const float* br = bw + row*3;
        const float* wv = gw + b*3;
        val = wv[0]*br[0] + wv[1]*br[1] + wv[2]*br[2];
    }
    lut[t] = __float2half_rn(val);
}

// ---- 6) AiLUT transform: table-searchsorted + 2-gather fp16 trilerp -------
__device__ __forceinline__ float coord_tab(float p, const float* __restrict__ v,
                                           const unsigned char* __restrict__ tab){
    int m = (int)(p*256.f); m = m < 0 ? 0 : (m > 255 ? 255 : m);
    int idx = tab[m];
    while (idx < 32 && v[idx] <= p) ++idx;
    while (idx > 1  && v[idx-1] > p) --idx;      // guard (float-rounding edge)
    float vl = v[idx-1], vh = v[idx];
    float f = (p - vl)/(vh - vl + 1e-8f);
    float c = (float)(idx-1) + f;
    return fminf(fmaxf(c, 0.f), 32.f);
}

__global__ void transform_kernel(const float* __restrict__ lq, const float* __restrict__ vert,
                                 const unsigned char* __restrict__ gtab,
                                 const __half* __restrict__ lut, float* __restrict__ out){
    __shared__ float sv[99];
    __shared__ unsigned char stab[768];
    const int b   = blockIdx.y;
    const int tid = threadIdx.x;
    if (tid < 99) sv[tid] = vert[b*99 + tid];
    for (int i = tid; i < 768; i += blockDim.x) stab[i] = gtab[b*768 + i];
    __syncthreads();
    const float* ib = lq  + (size_t)b*3*HWIN;
    float*       ob = out + (size_t)b*3*HWIN;
    const __half* lb = lut + (size_t)b*33*32*32*16;
    const int n0 = (blockIdx.x*blockDim.x + tid)*4;      // 4 consecutive px

    float4 rv = *(const float4*)(ib + n0);
    float4 gv = *(const float4*)(ib + HWIN + n0);
    float4 bv = *(const float4*)(ib + 2*HWIN + n0);
    float4 o0, o1, o2;
    float* rp = &rv.x; float* gp = &gv.x; float* bp = &bv.x;
    float* q0 = &o0.x; float* q1 = &o1.x; float* q2 = &o2.x;

    #pragma unroll
    for (int pp = 0; pp < 4; ++pp){
        float cr = coord_tab(rp[pp], sv,      stab);
        float cg = coord_tab(gp[pp], sv + 33, stab + 256);
        float cb = coord_tab(bp[pp], sv + 66, stab + 512);
        int i0 = (int)cr; i0 = i0 > 31 ? 31 : i0; float fr = cr - (float)i0;
        int j0 = (int)cg; j0 = j0 > 31 ? 31 : j0; float fg = cg - (float)j0;
        int k0 = (int)cb; k0 = k0 > 31 ? 31 : k0; float fk = cb - (float)k0;
        const __half* base = lb + (((i0*32 + j0) << 5) + k0)*16;
        float a0 = 0.f, a1 = 0.f, a2 = 0.f;
        float wdi[2] = {1.f - fr, fr};
        float wdj[2] = {1.f - fg, fg};
        #pragma unroll
        for (int di = 0; di < 2; ++di){
            const uint4* p = (const uint4*)(base + di*16384);
            uint4 qa = p[0];           // dj=0: dk0 ch0-3, dk1 ch0-3
            uint4 qb = p[1];           // dj=1
            float w0 = wdi[di]*wdj[0];
            float w1 = wdi[di]*wdj[1];
            {
                float2 l01 = __half22float2(*(const __half2*)&qa.x);
                float2 l2_ = __half22float2(*(const __half2*)&qa.y);
                float2 h01 = __half22float2(*(const __half2*)&qa.z);
                float2 h2_ = __half22float2(*(const __half2*)&qa.w);
                a0 += w0*(l01.x + fk*(h01.x - l01.x));
                a1 += w0*(l01.y + fk*(h01.y - l01.y));
                a2 += w0*(l2_.x + fk*(h2_.x - l2_.x));
            }
            {
                float2 l01 = __half22float2(*(const __half2*)&qb.x);
                float2 l2_ = __half22float2(*(const __half2*)&qb.y);
                float2 h01 = __half22float2(*(const __half2*)&qb.z);
                float2 h2_ = __half22float2(*(const __half2*)&qb.w);
                a0 += w1*(l01.x + fk*(h01.x - l01.x));
                a1 += w1*(l01.y + fk*(h01.y - l01.y));
                a2 += w1*(l2_.x + fk*(h2_.x - l2_.x));
            }
        }
        q0[pp] = fminf(fmaxf(a0, 0.f), 1.f);
        q1[pp] = fminf(fmaxf(a1, 0.f), 1.f);
        q2[pp] = fminf(fmaxf(a2, 0.f), 1.f);
    }
    *(float4*)(ob + n0)          = o0;
    *(float4*)(ob + HWIN + n0)   = o1;
    *(float4*)(ob + 2*HWIN + n0) = o2;
}

// ---------------------------------------------------------------------------
extern "C" void kernel_launch(void* const* d_in, const int* in_sizes, int n_in,
                              void* d_out, int out_size){
    const float* lq  = (const float*)d_in[0];
    const float* w1  = (const float*)d_in[1];
    const float* b1  = (const float*)d_in[2];
    const float* g1  = (const float*)d_in[3];
    const float* be1 = (const float*)d_in[4];
    const float* w2  = (const float*)d_in[5];
    const float* b2  = (const float*)d_in[6];
    const float* g2  = (const float*)d_in[7];
    const float* be2 = (const float*)d_in[8];
    const float* w3  = (const float*)d_in[9];
    const float* b3  = (const float*)d_in[10];
    const float* g3  = (const float*)d_in[11];
    const float* be3 = (const float*)d_in[12];
    const float* w4  = (const float*)d_in[13];
    const float* b4  = (const float*)d_in[14];
    const float* g4  = (const float*)d_in[15];
    const float* be4 = (const float*)d_in[16];
    const float* w5  = (const float*)d_in[17];
    const float* b5  = (const float*)d_in[18];
    const float* lw  = (const float*)d_in[19];
    const float* lb  = (const float*)d_in[20];
    const float* bw  = (const float*)d_in[21];
    const float* aw  = (const float*)d_in[22];
    const float* ab  = (const float*)d_in[23];
    float* out = (float*)d_out;

    float *x0,*x1,*x2,*x3,*x4,*codes,*wS,*vS;
    __half* lutp; unsigned char* tabp;
    cudaGetSymbolAddress((void**)&x0,    g_x0);
    cudaGetSymbolAddress((void**)&x1,    g_x1);
    cudaGetSymbolAddress((void**)&x2,    g_x2);
    cudaGetSymbolAddress((void**)&x3,    g_x3);
    cudaGetSymbolAddress((void**)&x4,    g_x4);
    cudaGetSymbolAddress((void**)&codes, g_codes);
    cudaGetSymbolAddress((void**)&wS,    g_wts);
    cudaGetSymbolAddress((void**)&vS,    g_vert);
    cudaGetSymbolAddress((void**)&lutp,  g_lut);
    cudaGetSymbolAddress((void**)&tabp,  g_tab);

    const size_t OFF_W = (size_t)BATCH*3*HWIN;   // 12,582,912
    const size_t OFF_V = OFF_W + BATCH*3;        // +12

    const int SM1 = (3*9*36  + 3*3*16*4)  * 4;
    const int SM2 = (16*9*20 + 16*3*32*4) * 4;
    const int SM3 = (32*9*20 + 32*3*32*4) * 4;   // 72192 B
    const int SM4 = (64*9*20 + 64*3*32*4) * 4;   // 144384 B
    cudaFuncSetAttribute((const void*)conv_tile<32,32,64,32,4,8,2>,
                         cudaFuncAttributeMaxDynamicSharedMemorySize, SM3);
    cudaFuncSetAttribute((const void*)conv_tile<64,32,32,16,4,8,2>,
                         cudaFuncAttributeMaxDynamicSharedMemorySize, SM4);

    resize_kernel<<<(BATCH*3*256*256)/256, 256>>>(lq, x0);

    conv_tile<3,16,256,128,4,16,2><<<dim3(32*8, 1, BATCH), 128, SM1>>>(x0, x1, w1, b1, 16);
    inorm<<<BATCH*16, 256>>>(x1, g1, be1, 16, 128*128);
    conv_tile<16,32,128,64,4,8,2><<<dim3(16*8, 1, BATCH), 128, SM2>>>(x1, x2, w2, b2, 32);
    inorm<<<BATCH*32, 256>>>(x2, g2, be2, 32, 64*64);
    conv_tile<32,32,64,32,4,8,2><<<dim3(8*4, 2, BATCH), 128, SM3>>>(x2, x3, w3, b3, 64);
    inorm<<<BATCH*64, 256>>>(x3, g3, be3, 64, 32*32);
    conv_tile<64,32,32,16,4,8,2><<<dim3(4*2, 4, BATCH), 128, SM4>>>(x3, x4, w4, b4, 128);
    inorm<<<BATCH*128, 256>>>(x4, g4, be4, 128, 16*16);

    conv5_pool<<<BATCH*128, 128>>>(x4, w5, b5, codes);
    fc_kernel<<<BATCH, 128>>>(codes, lw, lb, aw, ab, wS, vS, tabp, out + OFF_W, out + OFF_V);
    lutgen<<<(BATCH*33*32*32*16)/256, 256>>>(wS, bw, lutp);
    transform_kernel<<<dim3(HWIN/(256*4), BATCH), 256>>>(lq, vS, tabp, lutp, out);
}